// round 5
// baseline (speedup 1.0000x reference)
#include <cuda_runtime.h>
#include <cstdint>

#define CC   4
#define HH   4096
#define WW   4096
#define NPIX (HH*WW)          // per-channel pixels: 16777216
#define TT   8
#define THW  512
#define BINS 256
#define AREA (THW*THW)        // 262144
#define CLV  40960            // int(40.0 * AREA / BINS)
#define MMB  1024             // minmax blocks per channel
#define SROWS 8               // rows per apply strip

// ---------------- scratch (static device globals; no allocation) ------------
__device__ unsigned char      g_q[(size_t)CC * NPIX];        // quantized value 0..255
__device__ unsigned char      g_m[(size_t)CC * NPIX / 4];    // mask nibble per float4 group
__device__ int                g_hist[CC][TT*TT][BINS];
__device__ unsigned char      g_lut[CC][TT*TT][BINS];
__device__ float2             g_part[CC * MMB];              // per-block (min,max) partials
__device__ int                g_vmin2[CC], g_vmax2[CC];      // float bits (y >= 0 -> int trick)
__device__ unsigned int       g_nm[CC];                      // masked-pixel count

#define F_INF  __int_as_float(0x7F800000)
#define F_NINF __int_as_float((int)0xFF800000)

// pack two exactly-bf16-representable floats into one uint (lo, hi)
__device__ __forceinline__ unsigned int packbf(float lo, float hi) {
    return (__float_as_uint(lo) >> 16) | (__float_as_uint(hi) & 0xFFFF0000u);
}

// ---------------- pass 1: per-block masked min/max partials (+ init) --------
__global__ void k_minmax(const float* __restrict__ X, int c) {
    int bx = blockIdx.x, tid = threadIdx.x;

    if (tid < 16) ((int*)&g_hist[c][0][0])[bx * 16 + tid] = 0;   // 16384 ints / 1024 blocks
    if (bx == 0 && tid == 0) {
        g_vmin2[c] = 0x7F800000;
        g_vmax2[c] = (int)0xFF800000;
        g_nm[c] = 0u;
    }

    const float4* p = (const float4*)(X + (size_t)c * NPIX);
    int base = bx * 4096;
    float vmin = F_INF, vmax = F_NINF;
    #pragma unroll 4
    for (int it = 0; it < 16; ++it) {
        float4 v = p[base + it * 256 + tid];
        if (v.x > 0.f) { vmin = fminf(vmin, v.x); vmax = fmaxf(vmax, v.x); }
        if (v.y > 0.f) { vmin = fminf(vmin, v.y); vmax = fmaxf(vmax, v.y); }
        if (v.z > 0.f) { vmin = fminf(vmin, v.z); vmax = fmaxf(vmax, v.z); }
        if (v.w > 0.f) { vmin = fminf(vmin, v.w); vmax = fmaxf(vmax, v.w); }
    }
    __shared__ float smn[8], smx[8];
    #pragma unroll
    for (int o = 16; o; o >>= 1) {
        vmin = fminf(vmin, __shfl_down_sync(0xffffffffu, vmin, o));
        vmax = fmaxf(vmax, __shfl_down_sync(0xffffffffu, vmax, o));
    }
    if ((tid & 31) == 0) { smn[tid >> 5] = vmin; smx[tid >> 5] = vmax; }
    __syncthreads();
    if (tid == 0) {
        float a = F_INF, b = F_NINF;
        #pragma unroll
        for (int j = 0; j < 8; j++) { a = fminf(a, smn[j]); b = fmaxf(b, smx[j]); }
        g_part[c * MMB + bx] = make_float2(a, b);
    }
}

// --------- pass 2: quantize + tile histograms + masked-count -----------------
__global__ void k_quant(const float* __restrict__ X, int c) {
    int bx = blockIdx.x, tid = threadIdx.x;
    __shared__ int sh[TT * BINS];
    __shared__ float smn[8], smx[8], sfin[2];

    float vmin = F_INF, vmax = F_NINF;
    for (int j = tid; j < MMB; j += 256) {
        float2 pp = g_part[c * MMB + j];
        vmin = fminf(vmin, pp.x); vmax = fmaxf(vmax, pp.y);
    }
    #pragma unroll
    for (int o = 16; o; o >>= 1) {
        vmin = fminf(vmin, __shfl_down_sync(0xffffffffu, vmin, o));
        vmax = fmaxf(vmax, __shfl_down_sync(0xffffffffu, vmax, o));
    }
    if ((tid & 31) == 0) { smn[tid >> 5] = vmin; smx[tid >> 5] = vmax; }
    for (int j = tid; j < TT * BINS; j += 256) sh[j] = 0;
    __syncthreads();
    if (tid == 0) {
        float a = F_INF, b = F_NINF;
        #pragma unroll
        for (int j = 0; j < 8; j++) { a = fminf(a, smn[j]); b = fmaxf(b, smx[j]); }
        sfin[0] = a; sfin[1] = b;
    }
    __syncthreads();
    vmin = sfin[0]; vmax = sfin[1];
    bool  cond = vmax > 0.0f;
    float rng  = fmaxf(vmax - vmin, 1e-12f);
    float a255 = cond ? (255.0f / rng) : 0.0f;
    float b255 = cond ? (-vmin * a255) : 0.0f;

    const float4* p  = (const float4*)(X + (size_t)c * NPIX);
    uchar4*       q8 = (uchar4*)(g_q + (size_t)c * NPIX);
    unsigned char* mp = g_m + (size_t)c * (NPIX / 4);

    int base = bx * 8192;
    unsigned int nm = 0;

    #pragma unroll 4
    for (int it = 0; it < 32; ++it) {
        int i = base + it * 256 + tid;
        float4 v = p[i];
        int tx = (i & 1023) >> 7;
        float xs[4] = {v.x, v.y, v.z, v.w};
        unsigned char r[4]; unsigned int nib = 0;
        #pragma unroll
        for (int k = 0; k < 4; k++) {
            float x = xs[k];
            bool  m = x > 0.0f;
            float t = m ? fmaf(x, a255, b255) : 0.0f;
            float fb = fminf(fmaxf(floorf(t), 0.0f), 255.0f);
            int b = (int)fb;
            atomicAdd(&sh[tx * BINS + b], 1);
            r[k] = (unsigned char)b;
            nib |= (m ? 1u : 0u) << k;
        }
        nm += (unsigned int)__popc(nib);
        uchar4 o; o.x = r[0]; o.y = r[1]; o.z = r[2]; o.w = r[3];
        q8[i] = o;
        mp[i] = (unsigned char)nib;
    }
    __syncthreads();

    int ty = bx >> 6;
    for (int j = tid; j < TT * BINS; j += 256) {
        int v = sh[j];
        if (v) atomicAdd(&g_hist[c][ty * TT + (j >> 8)][j & 255], v);
    }
    #pragma unroll
    for (int o = 16; o; o >>= 1) nm += __shfl_down_sync(0xffffffffu, nm, o);
    if ((tid & 31) == 0) atomicAdd(&g_nm[c], nm);
}

// ------- pass 3: derive nz/sum/flag0 from hist, clip+redistribute+CDF -> LUT -
__global__ void k_lut(int c) {
    int tile = blockIdx.x, t = threadIdx.x;
    __shared__ unsigned int sa[BINS], sb[BINS];
    __shared__ int s[BINS];

    // column sums across all 64 tiles (exact integer stats)
    unsigned int colsum = 0;
    #pragma unroll
    for (int k = 0; k < TT * TT; k++) colsum += (unsigned int)g_hist[c][k][t];
    sa[t] = t ? colsum : 0u;                    // nz excludes bin 0
    sb[t] = (unsigned int)t * colsum;           // max 255*16.7M = 4.28e9, fits u32
    __syncthreads();
    #pragma unroll
    for (int o = 128; o; o >>= 1) {
        if (t < o) { sa[t] += sa[t + o]; sb[t] += sb[t + o]; }
        __syncthreads();
    }
    unsigned int nz = sa[0], sum = sb[0];

    if (tile == 0 && t == 0) {
        // masked pixels with bin 0 exist <=> bin0 total > unmasked count -> y=0 candidate
        unsigned int unmasked = (unsigned int)NPIX - g_nm[c];
        if (colsum > unmasked) { g_vmin2[c] = 0; g_vmax2[c] = 0; }
    }

    int mean = nz ? (int)(sum / nz) : 0;

    int h = g_hist[c][tile][t];
    if (nz && mean != 0) {                      // hist of `filled`: move bin0 -> mean
        int h0 = g_hist[c][tile][0];
        if (t == mean) h += h0;
        if (t == 0)    h  = 0;
    }

    int exc = max(h - CLV, 0);
    s[t] = exc; __syncthreads();
    #pragma unroll
    for (int o = 128; o; o >>= 1) { if (t < o) s[t] += s[t + o]; __syncthreads(); }
    int excess = s[0];
    __syncthreads();

    h = min(h, CLV);
    int batch = excess >> 8;
    int resid = excess & 255;
    int step  = 256 / max(resid, 1);
    h += batch + (((t % step) == 0 && (t / step) < resid) ? 1 : 0);

    s[t] = h; __syncthreads();
    #pragma unroll
    for (int o = 1; o < 256; o <<= 1) {
        int v = (t >= o) ? s[t - o] : 0;
        __syncthreads();
        s[t] += v;
        __syncthreads();
    }
    float lut = rintf((float)s[t] * (255.0f / (float)AREA));
    lut = fminf(fmaxf(lut, 0.0f), 255.0f);
    g_lut[c][tile][t] = (unsigned char)lut;
}

// -------- passes 4/5: 8-row strips, bf16-packed strip LUT, NaN-bin0 trick ----
template <bool FINAL>
__global__ void __launch_bounds__(256) k_apply(float* __restrict__ out, int c) {
    int s = blockIdx.x, tid = threadIdx.x;
    int r0 = s * SROWS;
    __shared__ uint2 lutP[9 * BINS];              // 18 KB

    float fy0 = ((float)r0 + 0.5f) * (1.0f / (float)THW) - 0.5f;
    int y0 = min(max((int)floorf(fy0), 0), TT - 1);
    int y1 = min(y0 + 1, TT - 1);

    const unsigned char* L = &g_lut[c][0][0];
    #pragma unroll
    for (int e0 = 0; e0 < 9 * BINS; e0 += 256) {
        int e = e0 + tid;
        int ix = e >> 8, f = e & 255;
        int xa = max(ix - 1, 0);
        int xb = min(xa + 1, TT - 1);
        if (f == 0) {
            // FINAL: eq must be exactly 0; pass0: NaN so FMNMX ignores it
            unsigned int z = FINAL ? 0u : 0x7FC07FC0u;
            lutP[e] = make_uint2(z, z);
        } else {
            float a0 = (float)L[(y0 * TT + xa) * BINS + f];
            float a1 = (float)L[(y0 * TT + xb) * BINS + f];
            float b0 = (float)L[(y1 * TT + xa) * BINS + f];
            float b1 = (float)L[(y1 * TT + xb) * BINS + f];
            lutP[e] = make_uint2(packbf(a0, a1 - a0), packbf(b0, b1 - b0));
        }
    }
    __syncthreads();

    float K1 = 0.0f, K2 = 0.0039215686f;
    if (FINAL) {
        float vmax2 = __int_as_float(g_vmax2[c]);
        float vmin2 = __int_as_float(g_vmin2[c]);
        if (vmax2 > 0.0f) {
            float rng2 = fmaxf(vmax2 - vmin2, 1e-12f);
            float k1 = 0.99607843137f / rng2;
            K1 = k1 * (1.0f / 255.0f);
            K2 = 0.0039215686f - vmin2 * k1;
        }
    }

    // per-thread column constants (16 contiguous columns share one ix slot)
    float fx0 = ((float)(tid * 16) + 0.5f) * (1.0f / (float)THW) - 0.5f;
    float ffx = floorf(fx0);
    float wx0 = fx0 - ffx;
    const uint2* rowL = lutP + ((int)ffx + 1) * BINS;
    float wxv[16];
    #pragma unroll
    for (int j = 0; j < 16; j++) wxv[j] = fmaf((float)j, 1.0f / (float)THW, wx0);

    int rowstride = WW / 16;
    size_t base16 = ((size_t)c * NPIX + (size_t)r0 * WW) >> 4;
    const uint4* qp = ((const uint4*)g_q) + base16 + tid;
    const unsigned int* mp = ((const unsigned int*)g_m) + base16 + tid;
    float4* op = ((float4*)out) + (((size_t)c * NPIX + (size_t)r0 * WW) >> 2) + tid * 4;

    float lmin = F_INF, lmax = F_NINF;

    for (int rr = 0; rr < SROWS; ++rr) {
        float fyr = ((float)(r0 + rr) + 0.5f) * (1.0f / (float)THW) - 0.5f;
        float wy = fyr - floorf(fyr);

        uint4 qw = qp[rr * rowstride];
        unsigned int mw = 0;
        if (FINAL) mw = mp[rr * rowstride];
        unsigned int wv[4] = {qw.x, qw.y, qw.z, qw.w};

        #pragma unroll
        for (int w = 0; w < 4; w++) {
            float res[4];
            #pragma unroll
            for (int k = 0; k < 4; k++) {
                unsigned int v = (wv[w] >> (8 * k)) & 255u;
                uint2 e = rowL[v];
                float a0 = __int_as_float(e.x << 16);
                float da = __int_as_float(e.x & 0xFFFF0000u);
                float b0 = __int_as_float(e.y << 16);
                float db = __int_as_float(e.y & 0xFFFF0000u);
                float wx = wxv[w * 4 + k];
                float px = fmaf(wx, da, a0);
                float qx = fmaf(wx, db, b0);
                float eq = fmaf(wy, qx - px, px);
                if (FINAL) {
                    float sc = fmaf(eq, K1, K2);
                    res[k] = ((mw >> (8 * w + k)) & 1u) ? sc : 0.0f;
                } else {
                    lmin = fminf(lmin, eq);        // NaN (bin0) ignored by FMNMX
                    lmax = fmaxf(lmax, eq);
                }
            }
            if (FINAL) {
                float4 o4; o4.x = res[0]; o4.y = res[1]; o4.z = res[2]; o4.w = res[3];
                op[(size_t)rr * (WW / 4) + w] = o4;
            }
        }
    }

    if (!FINAL) {
        __shared__ float smn[8], smx[8];
        #pragma unroll
        for (int o = 16; o; o >>= 1) {
            lmin = fminf(lmin, __shfl_down_sync(0xffffffffu, lmin, o));
            lmax = fmaxf(lmax, __shfl_down_sync(0xffffffffu, lmax, o));
        }
        if ((tid & 31) == 0) { smn[tid >> 5] = lmin; smx[tid >> 5] = lmax; }
        __syncthreads();
        if (tid == 0) {
            float a = F_INF, b = F_NINF;
            #pragma unroll
            for (int j = 0; j < 8; j++) { a = fminf(a, smn[j]); b = fmaxf(b, smx[j]); }
            a = a * (1.0f / 255.0f);              // y = eq/255 (monotone)
            b = b * (1.0f / 255.0f);
            atomicMin(&g_vmin2[c], __float_as_int(a));
            atomicMax(&g_vmax2[c], __float_as_int(b));
        }
    }
}

// ---------------------------------------------------------------------------
extern "C" void kernel_launch(void* const* d_in, const int* in_sizes, int n_in,
                              void* d_out, int out_size) {
    const float* X = (const float*)d_in[0];
    float* out = (float*)d_out;

    // per-channel phase ordering: each channel's working set stays L2-resident
    for (int c = 0; c < CC; c++) {
        k_minmax<<<MMB, 256>>>(X, c);
        k_quant <<<512, 256>>>(X, c);
        k_lut   <<<TT*TT, 256>>>(c);
        k_apply<false><<<HH/SROWS, 256>>>(out, c);
        k_apply<true> <<<HH/SROWS, 256>>>(out, c);
    }
}

// round 6
// speedup vs baseline: 1.2767x; 1.2767x over previous
#include <cuda_runtime.h>
#include <cstdint>

#define CC   4
#define HH   4096
#define WW   4096
#define NPIX (HH*WW)          // per-channel pixels: 16777216
#define TT   8
#define THW  512
#define BINS 256
#define AREA (THW*THW)        // 262144
#define CLV  40960            // int(40.0 * AREA / BINS)
#define MMB  1024             // minmax blocks per channel
#define SROWS 8               // rows per apply strip

// ---------------- scratch (static device globals; no allocation) ------------
__device__ unsigned char      g_q[(size_t)CC * NPIX];        // quantized value 0..255
__device__ unsigned char      g_m[(size_t)CC * NPIX / 4];    // mask nibble per float4 group
__device__ int                g_hist[CC][TT*TT][BINS];
__device__ unsigned char      g_lut[CC][TT*TT][BINS];
__device__ float2             g_part[CC * MMB];              // per-block (min,max) partials
__device__ int                g_vmin2[CC], g_vmax2[CC];      // float bits (y >= 0 -> int trick)
__device__ unsigned int       g_nm[CC];                      // masked-pixel count

#define F_INF  __int_as_float(0x7F800000)
#define F_NINF __int_as_float((int)0xFF800000)

// pack two exactly-bf16-representable floats into one uint (lo, hi)
__device__ __forceinline__ unsigned int packbf(float lo, float hi) {
    return (__float_as_uint(lo) >> 16) | (__float_as_uint(hi) & 0xFFFF0000u);
}

// ---------------- pass 1: per-block masked min/max partials (+ init) --------
__global__ void k_minmax(const float* __restrict__ X) {
    int c = blockIdx.y, bx = blockIdx.x, tid = threadIdx.x;

    if (tid < 16) ((int*)&g_hist[c][0][0])[bx * 16 + tid] = 0;   // 16384 ints / 1024 blocks
    if (bx == 0 && tid == 0) {
        g_vmin2[c] = 0x7F800000;
        g_vmax2[c] = (int)0xFF800000;
        g_nm[c] = 0u;
    }

    const float4* p = (const float4*)(X + (size_t)c * NPIX);
    int base = bx * 4096;
    float vmin = F_INF, vmax = F_NINF;
    #pragma unroll 4
    for (int it = 0; it < 16; ++it) {
        float4 v = p[base + it * 256 + tid];
        if (v.x > 0.f) { vmin = fminf(vmin, v.x); vmax = fmaxf(vmax, v.x); }
        if (v.y > 0.f) { vmin = fminf(vmin, v.y); vmax = fmaxf(vmax, v.y); }
        if (v.z > 0.f) { vmin = fminf(vmin, v.z); vmax = fmaxf(vmax, v.z); }
        if (v.w > 0.f) { vmin = fminf(vmin, v.w); vmax = fmaxf(vmax, v.w); }
    }
    __shared__ float smn[8], smx[8];
    #pragma unroll
    for (int o = 16; o; o >>= 1) {
        vmin = fminf(vmin, __shfl_down_sync(0xffffffffu, vmin, o));
        vmax = fmaxf(vmax, __shfl_down_sync(0xffffffffu, vmax, o));
    }
    if ((tid & 31) == 0) { smn[tid >> 5] = vmin; smx[tid >> 5] = vmax; }
    __syncthreads();
    if (tid == 0) {
        float a = F_INF, b = F_NINF;
        #pragma unroll
        for (int j = 0; j < 8; j++) { a = fminf(a, smn[j]); b = fmaxf(b, smx[j]); }
        g_part[c * MMB + bx] = make_float2(a, b);
    }
}

// --------- pass 2: quantize + tile histograms + masked-count -----------------
__global__ void k_quant(const float* __restrict__ X) {
    int c = blockIdx.y, bx = blockIdx.x, tid = threadIdx.x;
    __shared__ int sh[TT * BINS];
    __shared__ float smn[8], smx[8], sfin[2];

    float vmin = F_INF, vmax = F_NINF;
    for (int j = tid; j < MMB; j += 256) {
        float2 pp = g_part[c * MMB + j];
        vmin = fminf(vmin, pp.x); vmax = fmaxf(vmax, pp.y);
    }
    #pragma unroll
    for (int o = 16; o; o >>= 1) {
        vmin = fminf(vmin, __shfl_down_sync(0xffffffffu, vmin, o));
        vmax = fmaxf(vmax, __shfl_down_sync(0xffffffffu, vmax, o));
    }
    if ((tid & 31) == 0) { smn[tid >> 5] = vmin; smx[tid >> 5] = vmax; }
    for (int j = tid; j < TT * BINS; j += 256) sh[j] = 0;
    __syncthreads();
    if (tid == 0) {
        float a = F_INF, b = F_NINF;
        #pragma unroll
        for (int j = 0; j < 8; j++) { a = fminf(a, smn[j]); b = fmaxf(b, smx[j]); }
        sfin[0] = a; sfin[1] = b;
    }
    __syncthreads();
    vmin = sfin[0]; vmax = sfin[1];
    bool  cond = vmax > 0.0f;
    float rng  = fmaxf(vmax - vmin, 1e-12f);
    float a255 = cond ? (255.0f / rng) : 0.0f;
    float b255 = cond ? (-vmin * a255) : 0.0f;

    const float4* p  = (const float4*)(X + (size_t)c * NPIX);
    uchar4*       q8 = (uchar4*)(g_q + (size_t)c * NPIX);
    unsigned char* mp = g_m + (size_t)c * (NPIX / 4);

    int base = bx * 8192;
    unsigned int nm = 0;

    #pragma unroll 4
    for (int it = 0; it < 32; ++it) {
        int i = base + it * 256 + tid;
        float4 v = p[i];
        int tx = (i & 1023) >> 7;
        float xs[4] = {v.x, v.y, v.z, v.w};
        unsigned char r[4]; unsigned int nib = 0;
        #pragma unroll
        for (int k = 0; k < 4; k++) {
            float x = xs[k];
            bool  m = x > 0.0f;
            float t = m ? fmaf(x, a255, b255) : 0.0f;
            float fb = fminf(fmaxf(floorf(t), 0.0f), 255.0f);
            int b = (int)fb;
            atomicAdd(&sh[tx * BINS + b], 1);
            r[k] = (unsigned char)b;
            nib |= (m ? 1u : 0u) << k;
        }
        nm += (unsigned int)__popc(nib);
        uchar4 o; o.x = r[0]; o.y = r[1]; o.z = r[2]; o.w = r[3];
        q8[i] = o;
        mp[i] = (unsigned char)nib;
    }
    __syncthreads();

    int ty = bx >> 6;
    for (int j = tid; j < TT * BINS; j += 256) {
        int v = sh[j];
        if (v) atomicAdd(&g_hist[c][ty * TT + (j >> 8)][j & 255], v);
    }
    #pragma unroll
    for (int o = 16; o; o >>= 1) nm += __shfl_down_sync(0xffffffffu, nm, o);
    if ((tid & 31) == 0) atomicAdd(&g_nm[c], nm);
}

// ------- pass 3: derive nz/sum/flag0 from hist, clip+redistribute+CDF -> LUT -
__global__ void k_lut() {
    int c = blockIdx.y, tile = blockIdx.x, t = threadIdx.x;
    __shared__ unsigned int sa[BINS], sb[BINS];
    __shared__ int s[BINS];

    // column sums across all 64 tiles (exact integer stats)
    unsigned int colsum = 0;
    #pragma unroll
    for (int k = 0; k < TT * TT; k++) colsum += (unsigned int)g_hist[c][k][t];
    sa[t] = t ? colsum : 0u;                    // nz excludes bin 0
    sb[t] = (unsigned int)t * colsum;           // max 255*16.7M = 4.28e9, fits u32
    __syncthreads();
    #pragma unroll
    for (int o = 128; o; o >>= 1) {
        if (t < o) { sa[t] += sa[t + o]; sb[t] += sb[t + o]; }
        __syncthreads();
    }
    unsigned int nz = sa[0], sum = sb[0];

    if (tile == 0 && t == 0) {
        // masked pixels with bin 0 exist <=> bin0 total > unmasked count -> y=0 candidate
        unsigned int unmasked = (unsigned int)NPIX - g_nm[c];
        if (colsum > unmasked) { g_vmin2[c] = 0; g_vmax2[c] = 0; }
    }

    int mean = nz ? (int)(sum / nz) : 0;

    int h = g_hist[c][tile][t];
    if (nz && mean != 0) {                      // hist of `filled`: move bin0 -> mean
        int h0 = g_hist[c][tile][0];
        if (t == mean) h += h0;
        if (t == 0)    h  = 0;
    }

    int exc = max(h - CLV, 0);
    s[t] = exc; __syncthreads();
    #pragma unroll
    for (int o = 128; o; o >>= 1) { if (t < o) s[t] += s[t + o]; __syncthreads(); }
    int excess = s[0];
    __syncthreads();

    h = min(h, CLV);
    int batch = excess >> 8;
    int resid = excess & 255;
    int step  = 256 / max(resid, 1);
    h += batch + (((t % step) == 0 && (t / step) < resid) ? 1 : 0);

    s[t] = h; __syncthreads();
    #pragma unroll
    for (int o = 1; o < 256; o <<= 1) {
        int v = (t >= o) ? s[t - o] : 0;
        __syncthreads();
        s[t] += v;
        __syncthreads();
    }
    float lut = rintf((float)s[t] * (255.0f / (float)AREA));
    lut = fminf(fmaxf(lut, 0.0f), 255.0f);
    g_lut[c][tile][t] = (unsigned char)lut;
}

// -------- passes 4/5: 8-row strips, bf16-packed strip LUT, NaN-bin0 trick ----
template <bool FINAL>
__global__ void __launch_bounds__(256) k_apply(float* __restrict__ out) {
    int c = blockIdx.y, s = blockIdx.x, tid = threadIdx.x;
    int r0 = s * SROWS;
    __shared__ uint2 lutP[9 * BINS];              // 18 KB

    float fy0 = ((float)r0 + 0.5f) * (1.0f / (float)THW) - 0.5f;
    int y0 = min(max((int)floorf(fy0), 0), TT - 1);
    int y1 = min(y0 + 1, TT - 1);

    const unsigned char* L = &g_lut[c][0][0];
    #pragma unroll
    for (int e0 = 0; e0 < 9 * BINS; e0 += 256) {
        int e = e0 + tid;
        int ix = e >> 8, f = e & 255;
        int xa = max(ix - 1, 0);
        int xb = min(xa + 1, TT - 1);
        if (f == 0) {
            // FINAL: eq must be exactly 0; pass0: NaN so FMNMX ignores it
            unsigned int z = FINAL ? 0u : 0x7FC07FC0u;
            lutP[e] = make_uint2(z, z);
        } else {
            float a0 = (float)L[(y0 * TT + xa) * BINS + f];
            float a1 = (float)L[(y0 * TT + xb) * BINS + f];
            float b0 = (float)L[(y1 * TT + xa) * BINS + f];
            float b1 = (float)L[(y1 * TT + xb) * BINS + f];
            lutP[e] = make_uint2(packbf(a0, a1 - a0), packbf(b0, b1 - b0));
        }
    }
    __syncthreads();

    float K1 = 0.0f, K2 = 0.0039215686f;
    if (FINAL) {
        float vmax2 = __int_as_float(g_vmax2[c]);
        float vmin2 = __int_as_float(g_vmin2[c]);
        if (vmax2 > 0.0f) {
            float rng2 = fmaxf(vmax2 - vmin2, 1e-12f);
            float k1 = 0.99607843137f / rng2;
            K1 = k1 * (1.0f / 255.0f);
            K2 = 0.0039215686f - vmin2 * k1;
        }
    }

    // per-thread column constants (16 contiguous columns share one ix slot)
    float fx0 = ((float)(tid * 16) + 0.5f) * (1.0f / (float)THW) - 0.5f;
    float ffx = floorf(fx0);
    float wx0 = fx0 - ffx;
    const uint2* rowL = lutP + ((int)ffx + 1) * BINS;
    float wxv[16];
    #pragma unroll
    for (int j = 0; j < 16; j++) wxv[j] = fmaf((float)j, 1.0f / (float)THW, wx0);

    int rowstride = WW / 16;
    size_t base16 = ((size_t)c * NPIX + (size_t)r0 * WW) >> 4;
    const uint4* qp = ((const uint4*)g_q) + base16 + tid;
    const unsigned int* mp = ((const unsigned int*)g_m) + base16 + tid;
    float4* op = ((float4*)out) + (((size_t)c * NPIX + (size_t)r0 * WW) >> 2) + tid * 4;

    float lmin = F_INF, lmax = F_NINF;

    for (int rr = 0; rr < SROWS; ++rr) {
        float fyr = ((float)(r0 + rr) + 0.5f) * (1.0f / (float)THW) - 0.5f;
        float wy = fyr - floorf(fyr);

        uint4 qw = qp[rr * rowstride];
        unsigned int mw = 0;
        if (FINAL) mw = mp[rr * rowstride];
        unsigned int wv[4] = {qw.x, qw.y, qw.z, qw.w};

        #pragma unroll
        for (int w = 0; w < 4; w++) {
            float res[4];
            #pragma unroll
            for (int k = 0; k < 4; k++) {
                unsigned int v = (wv[w] >> (8 * k)) & 255u;
                uint2 e = rowL[v];
                float a0 = __int_as_float(e.x << 16);
                float da = __int_as_float(e.x & 0xFFFF0000u);
                float b0 = __int_as_float(e.y << 16);
                float db = __int_as_float(e.y & 0xFFFF0000u);
                float wx = wxv[w * 4 + k];
                float px = fmaf(wx, da, a0);
                float qx = fmaf(wx, db, b0);
                float eq = fmaf(wy, qx - px, px);
                if (FINAL) {
                    float sc = fmaf(eq, K1, K2);
                    res[k] = ((mw >> (8 * w + k)) & 1u) ? sc : 0.0f;
                } else {
                    lmin = fminf(lmin, eq);        // NaN (bin0) ignored by FMNMX
                    lmax = fmaxf(lmax, eq);
                }
            }
            if (FINAL) {
                float4 o4; o4.x = res[0]; o4.y = res[1]; o4.z = res[2]; o4.w = res[3];
                op[(size_t)rr * (WW / 4) + w] = o4;
            }
        }
    }

    if (!FINAL) {
        __shared__ float smn[8], smx[8];
        #pragma unroll
        for (int o = 16; o; o >>= 1) {
            lmin = fminf(lmin, __shfl_down_sync(0xffffffffu, lmin, o));
            lmax = fmaxf(lmax, __shfl_down_sync(0xffffffffu, lmax, o));
        }
        if ((tid & 31) == 0) { smn[tid >> 5] = lmin; smx[tid >> 5] = lmax; }
        __syncthreads();
        if (tid == 0) {
            float a = F_INF, b = F_NINF;
            #pragma unroll
            for (int j = 0; j < 8; j++) { a = fminf(a, smn[j]); b = fmaxf(b, smx[j]); }
            a = a * (1.0f / 255.0f);              // y = eq/255 (monotone)
            b = b * (1.0f / 255.0f);
            atomicMin(&g_vmin2[c], __float_as_int(a));
            atomicMax(&g_vmax2[c], __float_as_int(b));
        }
    }
}

// ---------------------------------------------------------------------------
extern "C" void kernel_launch(void* const* d_in, const int* in_sizes, int n_in,
                              void* d_out, int out_size) {
    const float* X = (const float*)d_in[0];
    float* out = (float*)d_out;

    dim3 g1(MMB, CC);        k_minmax<<<g1, 256>>>(X);
    dim3 g2(512, CC);        k_quant <<<g2, 256>>>(X);
    dim3 g3(TT*TT, CC);      k_lut   <<<g3, 256>>>();
    dim3 g4(HH/SROWS, CC);
    k_apply<false><<<g4, 256>>>(out);
    k_apply<true> <<<g4, 256>>>(out);
}

// round 7
// speedup vs baseline: 1.4557x; 1.1402x over previous
#include <cuda_runtime.h>
#include <cstdint>

#define CC   4
#define HH   4096
#define WW   4096
#define NPIX (HH*WW)          // per-channel pixels: 16777216
#define TT   8
#define THW  512
#define BINS 256
#define AREA (THW*THW)        // 262144
#define CLV  40960            // int(40.0 * AREA / BINS)
#define MMB  1024             // minmax blocks per channel
#define SROWS 8               // rows per apply strip
#define QH   16               // quadrant halves per dim (256-px)

// ---------------- scratch (static device globals; no allocation) ------------
__device__ unsigned char      g_q[(size_t)CC * NPIX];        // quantized value 0..255
__device__ unsigned char      g_m[(size_t)CC * NPIX / 4];    // mask nibble per float4 group
__device__ int                g_qh[CC][QH][QH][BINS];        // quadrant histograms (1 MB)
__device__ unsigned char      g_lut[CC][TT*TT][BINS];
__device__ float2             g_part[CC * MMB];              // per-block (min,max) partials
__device__ int                g_vmin2[CC], g_vmax2[CC];      // float bits (y >= 0 -> int trick)
__device__ unsigned int       g_nm[CC];                      // masked-pixel count

#define F_INF  __int_as_float(0x7F800000)
#define F_NINF __int_as_float((int)0xFF800000)

// pack two exactly-bf16-representable floats into one uint (lo, hi)
__device__ __forceinline__ unsigned int packbf(float lo, float hi) {
    return (__float_as_uint(lo) >> 16) | (__float_as_uint(hi) & 0xFFFF0000u);
}

// ---------------- pass 1: per-block masked min/max partials (+ init) --------
__global__ void k_minmax(const float* __restrict__ X) {
    int c = blockIdx.y, bx = blockIdx.x, tid = threadIdx.x;

    // zero quadrant hists: 16*16*256 = 65536 ints over 1024 blocks = 64 each
    if (tid < 64) ((int*)&g_qh[c][0][0][0])[bx * 64 + tid] = 0;
    if (bx == 0 && tid == 0) {
        g_vmin2[c] = 0x7F800000;
        g_vmax2[c] = (int)0xFF800000;
        g_nm[c] = 0u;
    }

    const float4* p = (const float4*)(X + (size_t)c * NPIX);
    int base = bx * 4096;
    float vmin = F_INF, vmax = F_NINF;
    #pragma unroll 4
    for (int it = 0; it < 16; ++it) {
        float4 v = p[base + it * 256 + tid];
        if (v.x > 0.f) { vmin = fminf(vmin, v.x); vmax = fmaxf(vmax, v.x); }
        if (v.y > 0.f) { vmin = fminf(vmin, v.y); vmax = fmaxf(vmax, v.y); }
        if (v.z > 0.f) { vmin = fminf(vmin, v.z); vmax = fmaxf(vmax, v.z); }
        if (v.w > 0.f) { vmin = fminf(vmin, v.w); vmax = fmaxf(vmax, v.w); }
    }
    __shared__ float smn[8], smx[8];
    #pragma unroll
    for (int o = 16; o; o >>= 1) {
        vmin = fminf(vmin, __shfl_down_sync(0xffffffffu, vmin, o));
        vmax = fmaxf(vmax, __shfl_down_sync(0xffffffffu, vmax, o));
    }
    if ((tid & 31) == 0) { smn[tid >> 5] = vmin; smx[tid >> 5] = vmax; }
    __syncthreads();
    if (tid == 0) {
        float a = F_INF, b = F_NINF;
        #pragma unroll
        for (int j = 0; j < 8; j++) { a = fminf(a, smn[j]); b = fmaxf(b, smx[j]); }
        g_part[c * MMB + bx] = make_float2(a, b);
    }
}

// --------- pass 2: quantize + QUADRANT histograms + masked-count -------------
__global__ void k_quant(const float* __restrict__ X) {
    int c = blockIdx.y, bx = blockIdx.x, tid = threadIdx.x;
    __shared__ int sh[QH * BINS];                 // 16 x-halves * 256 bins = 16 KB
    __shared__ float smn[8], smx[8], sfin[2];

    float vmin = F_INF, vmax = F_NINF;
    for (int j = tid; j < MMB; j += 256) {
        float2 pp = g_part[c * MMB + j];
        vmin = fminf(vmin, pp.x); vmax = fmaxf(vmax, pp.y);
    }
    #pragma unroll
    for (int o = 16; o; o >>= 1) {
        vmin = fminf(vmin, __shfl_down_sync(0xffffffffu, vmin, o));
        vmax = fmaxf(vmax, __shfl_down_sync(0xffffffffu, vmax, o));
    }
    if ((tid & 31) == 0) { smn[tid >> 5] = vmin; smx[tid >> 5] = vmax; }
    for (int j = tid; j < QH * BINS; j += 256) sh[j] = 0;
    __syncthreads();
    if (tid == 0) {
        float a = F_INF, b = F_NINF;
        #pragma unroll
        for (int j = 0; j < 8; j++) { a = fminf(a, smn[j]); b = fmaxf(b, smx[j]); }
        sfin[0] = a; sfin[1] = b;
    }
    __syncthreads();
    vmin = sfin[0]; vmax = sfin[1];
    bool  cond = vmax > 0.0f;
    float rng  = fmaxf(vmax - vmin, 1e-12f);
    float a255 = cond ? (255.0f / rng) : 0.0f;
    float b255 = cond ? (-vmin * a255) : 0.0f;

    const float4* p  = (const float4*)(X + (size_t)c * NPIX);
    uchar4*       q8 = (uchar4*)(g_q + (size_t)c * NPIX);
    unsigned char* mp = g_m + (size_t)c * (NPIX / 4);

    int base = bx * 8192;                         // 8 rows of 1024 float4
    unsigned int nm = 0;

    #pragma unroll 4
    for (int it = 0; it < 32; ++it) {
        int i = base + it * 256 + tid;
        float4 v = p[i];
        int tx = (i & 1023) >> 6;                 // 64 float4 per 256-px half
        float xs[4] = {v.x, v.y, v.z, v.w};
        unsigned char r[4]; unsigned int nib = 0;
        #pragma unroll
        for (int k = 0; k < 4; k++) {
            float x = xs[k];
            bool  m = x > 0.0f;
            float t = m ? fmaf(x, a255, b255) : 0.0f;
            float fb = fminf(fmaxf(floorf(t), 0.0f), 255.0f);
            int b = (int)fb;
            atomicAdd(&sh[tx * BINS + b], 1);
            r[k] = (unsigned char)b;
            nib |= (m ? 1u : 0u) << k;
        }
        nm += (unsigned int)__popc(nib);
        uchar4 o; o.x = r[0]; o.y = r[1]; o.z = r[2]; o.w = r[3];
        q8[i] = o;
        mp[i] = (unsigned char)nib;
    }
    __syncthreads();

    int yh = bx >> 5;                             // 32 blocks (8 rows each) per 256-row half
    int* gq = &g_qh[c][yh][0][0];
    for (int j = tid; j < QH * BINS; j += 256) {
        int v = sh[j];
        if (v) atomicAdd(&gq[j], v);
    }
    #pragma unroll
    for (int o = 16; o; o >>= 1) nm += __shfl_down_sync(0xffffffffu, nm, o);
    if ((tid & 31) == 0) atomicAdd(&g_nm[c], nm);
}

// ------- pass 3: derive stats from quadrant hists, clip+redistribute+CDF ----
__global__ void k_lut() {
    int c = blockIdx.y, tile = blockIdx.x, t = threadIdx.x;
    __shared__ unsigned int sa[BINS], sb[BINS];
    __shared__ int s[BINS];

    const int* Q = &g_qh[c][0][0][0];

    // channel column sums across all 256 quadrants (exact integer stats)
    unsigned int colsum = 0;
    #pragma unroll 8
    for (int k = 0; k < QH * QH; k++) colsum += (unsigned int)Q[k * BINS + t];
    sa[t] = t ? colsum : 0u;                      // nz excludes bin 0
    sb[t] = (unsigned int)t * colsum;             // max 255*16.7M < 2^32
    __syncthreads();
    #pragma unroll
    for (int o = 128; o; o >>= 1) {
        if (t < o) { sa[t] += sa[t + o]; sb[t] += sb[t + o]; }
        __syncthreads();
    }
    unsigned int nz = sa[0], sum = sb[0];

    if (tile == 0 && t == 0) {
        // masked bin-0 pixel exists <=> bin0 total > unmasked count -> y=0 candidate
        unsigned int unmasked = (unsigned int)NPIX - g_nm[c];
        if (colsum > unmasked) { g_vmin2[c] = 0; g_vmax2[c] = 0; }
    }

    int mean = nz ? (int)(sum / nz) : 0;

    // tile hist = sum of its 4 quadrants
    int ty = tile >> 3, tx = tile & 7;
    int q00 = ((2 * ty) * QH + 2 * tx) * BINS;
    int q01 = q00 + BINS;
    int q10 = q00 + QH * BINS;
    int q11 = q10 + BINS;
    int h  = Q[q00 + t] + Q[q01 + t] + Q[q10 + t] + Q[q11 + t];
    if (nz && mean != 0) {                        // hist of `filled`: move bin0 -> mean
        int h0 = Q[q00] + Q[q01] + Q[q10] + Q[q11];
        if (t == mean) h += h0;
        if (t == 0)    h  = 0;
    }

    int exc = max(h - CLV, 0);
    s[t] = exc; __syncthreads();
    #pragma unroll
    for (int o = 128; o; o >>= 1) { if (t < o) s[t] += s[t + o]; __syncthreads(); }
    int excess = s[0];
    __syncthreads();

    h = min(h, CLV);
    int batch = excess >> 8;
    int resid = excess & 255;
    int step  = 256 / max(resid, 1);
    h += batch + (((t % step) == 0 && (t / step) < resid) ? 1 : 0);

    s[t] = h; __syncthreads();
    #pragma unroll
    for (int o = 1; o < 256; o <<= 1) {
        int v = (t >= o) ? s[t - o] : 0;
        __syncthreads();
        s[t] += v;
        __syncthreads();
    }
    float lut = rintf((float)s[t] * (255.0f / (float)AREA));
    lut = fminf(fmaxf(lut, 0.0f), 255.0f);
    g_lut[c][tile][t] = (unsigned char)lut;
}

// ---- pass 4 (analytic): eq is bilinear per (region, bin); extremes at the 4
// ---- corner pixels of each 9x9 dual region. 81 blocks/channel, exact. -------
__global__ void k_mm2() {
    int c = blockIdx.y, reg = blockIdx.x, t = threadIdx.x;
    int ry = reg / 9, rx = reg % 9;

    // pixel ranges where floor(fy)==ry-1 / floor(fx)==rx-1
    int rlo = (ry == 0) ? 0 : 512 * ry - 256;
    int rhi = (ry == 8) ? (HH - 1) : 512 * ry + 255;
    int clo = (rx == 0) ? 0 : 512 * rx - 256;
    int chi = (rx == 8) ? (WW - 1) : 512 * rx + 255;

    // presence: bins v>=1 are exactly "masked pixel with bin v"
    bool pres = false;
    if (t > 0) {
        int yh0 = rlo >> 8, yh1 = rhi >> 8;
        int xh0 = clo >> 8, xh1 = chi >> 8;
        for (int yh = yh0; yh <= yh1; ++yh)
            for (int xh = xh0; xh <= xh1; ++xh)
                pres |= (g_qh[c][yh][xh][t] > 0);
    }

    float lmin = F_INF, lmax = F_NINF;
    if (pres) {
        int y0 = max(ry - 1, 0); int y1 = min(y0 + 1, TT - 1);
        int xa = max(rx - 1, 0); int xb = min(xa + 1, TT - 1);
        const unsigned char* L = &g_lut[c][0][0];
        float a0 = (float)L[(y0 * TT + xa) * BINS + t];
        float da = (float)L[(y0 * TT + xb) * BINS + t] - a0;
        float b0 = (float)L[(y1 * TT + xa) * BINS + t];
        float db = (float)L[(y1 * TT + xb) * BINS + t] - b0;

        // corner wy / wx, computed exactly like the apply kernel does
        float fyl = ((float)rlo + 0.5f) * (1.0f / (float)THW) - 0.5f;
        float fyh = ((float)rhi + 0.5f) * (1.0f / (float)THW) - 0.5f;
        float wyv[2] = { fyl - floorf(fyl), fyh - floorf(fyh) };
        float fxl = ((float)clo + 0.5f) * (1.0f / (float)THW) - 0.5f;
        float fxh = ((float)chi + 0.5f) * (1.0f / (float)THW) - 0.5f;
        float wxv[2] = { fxl - floorf(fxl), fxh - floorf(fxh) };

        #pragma unroll
        for (int jy = 0; jy < 2; jy++) {
            #pragma unroll
            for (int jx = 0; jx < 2; jx++) {
                float px = fmaf(wxv[jx], da, a0);
                float qx = fmaf(wxv[jx], db, b0);
                float eq = fmaf(wyv[jy], qx - px, px);
                lmin = fminf(lmin, eq);
                lmax = fmaxf(lmax, eq);
            }
        }
    }

    __shared__ float smn[8], smx[8];
    #pragma unroll
    for (int o = 16; o; o >>= 1) {
        lmin = fminf(lmin, __shfl_down_sync(0xffffffffu, lmin, o));
        lmax = fmaxf(lmax, __shfl_down_sync(0xffffffffu, lmax, o));
    }
    if ((t & 31) == 0) { smn[t >> 5] = lmin; smx[t >> 5] = lmax; }
    __syncthreads();
    if (t == 0) {
        float a = F_INF, b = F_NINF;
        #pragma unroll
        for (int j = 0; j < 8; j++) { a = fminf(a, smn[j]); b = fmaxf(b, smx[j]); }
        if (b != F_NINF) {                        // something present
            a = a * (1.0f / 255.0f);              // y = eq/255 (monotone)
            b = b * (1.0f / 255.0f);
            atomicMin(&g_vmin2[c], __float_as_int(a));
            atomicMax(&g_vmax2[c], __float_as_int(b));
        }
    }
}

// -------- pass 5: 8-row strips, bf16-packed strip LUT, final write ----------
__global__ void __launch_bounds__(256) k_apply(float* __restrict__ out) {
    int c = blockIdx.y, s = blockIdx.x, tid = threadIdx.x;
    int r0 = s * SROWS;
    __shared__ uint2 lutP[9 * BINS];              // 18 KB

    float fy0 = ((float)r0 + 0.5f) * (1.0f / (float)THW) - 0.5f;
    int y0 = min(max((int)floorf(fy0), 0), TT - 1);
    int y1 = min(y0 + 1, TT - 1);

    const unsigned char* L = &g_lut[c][0][0];
    #pragma unroll
    for (int e0 = 0; e0 < 9 * BINS; e0 += 256) {
        int e = e0 + tid;
        int ix = e >> 8, f = e & 255;
        int xa = max(ix - 1, 0);
        int xb = min(xa + 1, TT - 1);
        if (f == 0) {
            lutP[e] = make_uint2(0u, 0u);         // eq must be exactly 0 for bin 0
        } else {
            float a0 = (float)L[(y0 * TT + xa) * BINS + f];
            float a1 = (float)L[(y0 * TT + xb) * BINS + f];
            float b0 = (float)L[(y1 * TT + xa) * BINS + f];
            float b1 = (float)L[(y1 * TT + xb) * BINS + f];
            lutP[e] = make_uint2(packbf(a0, a1 - a0), packbf(b0, b1 - b0));
        }
    }
    __syncthreads();

    float K1 = 0.0f, K2 = 0.0039215686f;
    {
        float vmax2 = __int_as_float(g_vmax2[c]);
        float vmin2 = __int_as_float(g_vmin2[c]);
        if (vmax2 > 0.0f) {
            float rng2 = fmaxf(vmax2 - vmin2, 1e-12f);
            float k1 = 0.99607843137f / rng2;
            K1 = k1 * (1.0f / 255.0f);
            K2 = 0.0039215686f - vmin2 * k1;
        }
    }

    float fx0 = ((float)(tid * 16) + 0.5f) * (1.0f / (float)THW) - 0.5f;
    float ffx = floorf(fx0);
    float wx0 = fx0 - ffx;
    const uint2* rowL = lutP + ((int)ffx + 1) * BINS;
    float wxv[16];
    #pragma unroll
    for (int j = 0; j < 16; j++) wxv[j] = fmaf((float)j, 1.0f / (float)THW, wx0);

    int rowstride = WW / 16;
    size_t base16 = ((size_t)c * NPIX + (size_t)r0 * WW) >> 4;
    const uint4* qp = ((const uint4*)g_q) + base16 + tid;
    const unsigned int* mp = ((const unsigned int*)g_m) + base16 + tid;
    float4* op = ((float4*)out) + (((size_t)c * NPIX + (size_t)r0 * WW) >> 2) + tid * 4;

    for (int rr = 0; rr < SROWS; ++rr) {
        float fyr = ((float)(r0 + rr) + 0.5f) * (1.0f / (float)THW) - 0.5f;
        float wy = fyr - floorf(fyr);

        uint4 qw = qp[rr * rowstride];
        unsigned int mw = mp[rr * rowstride];
        unsigned int wv[4] = {qw.x, qw.y, qw.z, qw.w};

        #pragma unroll
        for (int w = 0; w < 4; w++) {
            float res[4];
            #pragma unroll
            for (int k = 0; k < 4; k++) {
                unsigned int v = (wv[w] >> (8 * k)) & 255u;
                uint2 e = rowL[v];
                float a0 = __int_as_float(e.x << 16);
                float da = __int_as_float(e.x & 0xFFFF0000u);
                float b0 = __int_as_float(e.y << 16);
                float db = __int_as_float(e.y & 0xFFFF0000u);
                float wx = wxv[w * 4 + k];
                float px = fmaf(wx, da, a0);
                float qx = fmaf(wx, db, b0);
                float eq = fmaf(wy, qx - px, px);
                float sc = fmaf(eq, K1, K2);
                res[k] = ((mw >> (8 * w + k)) & 1u) ? sc : 0.0f;
            }
            float4 o4; o4.x = res[0]; o4.y = res[1]; o4.z = res[2]; o4.w = res[3];
            op[(size_t)rr * (WW / 4) + w] = o4;
        }
    }
}

// ---------------------------------------------------------------------------
extern "C" void kernel_launch(void* const* d_in, const int* in_sizes, int n_in,
                              void* d_out, int out_size) {
    const float* X = (const float*)d_in[0];
    float* out = (float*)d_out;

    dim3 g1(MMB, CC);        k_minmax<<<g1, 256>>>(X);
    dim3 g2(512, CC);        k_quant <<<g2, 256>>>(X);
    dim3 g3(TT*TT, CC);      k_lut   <<<g3, 256>>>();
    dim3 g5(81, CC);         k_mm2   <<<g5, 256>>>();
    dim3 g4(HH/SROWS, CC);   k_apply <<<g4, 256>>>(out);
}